// round 3
// baseline (speedup 1.0000x reference)
#include <cuda_runtime.h>

#define G    4096
#define NPG  32
#define NN   (G * NPG)      // 131072
#define D    256
#define SH   256
#define HDG  50
#define HDN  3

// Output layout (flattened tuple): g_head[G,50], n_head[N,3], g_var[G,50], n_var[N,3]
#define OFF_GHEAD 0
#define OFF_NHEAD (G * HDG)                    // 204800
#define OFF_GVAR  (G * HDG + NN * HDN)         // 598016
#define OFF_NVAR  (2 * G * HDG + NN * HDN)     // 802816

// Scratch: per-graph mean of x  (4 MB, static device allocation — allowed)
__device__ float g_xg[G * D];

// ---------------------------------------------------------------------------
// Kernel 1: segment mean. batch = arange(N)//32 -> graphs are contiguous
// 32-row blocks, counts are all 32.
// ---------------------------------------------------------------------------
__global__ void mean_k(const float* __restrict__ x)
{
    int g = blockIdx.x;
    int d = threadIdx.x;
    const float* xp = x + (size_t)g * NPG * D + d;
    float s = 0.f;
#pragma unroll
    for (int i = 0; i < NPG; i++) s += xp[i * D];
    g_xg[g * D + d] = s * (1.0f / NPG);
}

// ---------------------------------------------------------------------------
// Shared GEMM core: 32 rows x 256 cols, K=256, fp32.
// Register tile 4 rows x (4+4) cols per thread; column blocks at c0 and
// c0+128 with c0 = lane*4 (conflict-free LDS.128: lane i reads byte 16*i).
// Rows: r0 = warp*4 (warp-uniform xs reads -> smem broadcast).
// Result (bias+ReLU applied) written back into xs[row*256 + col].
// ---------------------------------------------------------------------------
__device__ __forceinline__ void mlp1_core(
    float* __restrict__ xs, float* __restrict__ ws,
    const float* __restrict__ W, const float* __restrict__ bias,
    int tid)
{
    int r0 = (tid >> 5) * 4;    // row base
    int c0 = (tid & 31) * 4;    // col base (block 0); block 1 at c0+128

    float acc[4][8];
#pragma unroll
    for (int r = 0; r < 4; r++)
#pragma unroll
        for (int c = 0; c < 8; c++) acc[r][c] = 0.f;

    for (int kt = 0; kt < D; kt += 16) {
        __syncthreads();
        const float4* wsrc = (const float4*)(W + (size_t)kt * SH);
        float4* wdst = (float4*)ws;
#pragma unroll
        for (int j = tid; j < 16 * SH / 4; j += 256) wdst[j] = wsrc[j];
        __syncthreads();
#pragma unroll
        for (int dd = 0; dd < 16; dd++) {
            float xv0 = xs[(r0 + 0) * D + kt + dd];
            float xv1 = xs[(r0 + 1) * D + kt + dd];
            float xv2 = xs[(r0 + 2) * D + kt + dd];
            float xv3 = xs[(r0 + 3) * D + kt + dd];
            float4 wa = *(const float4*)&ws[dd * SH + c0];
            float4 wb = *(const float4*)&ws[dd * SH + c0 + 128];
            float wv[8] = {wa.x, wa.y, wa.z, wa.w, wb.x, wb.y, wb.z, wb.w};
#pragma unroll
            for (int c = 0; c < 8; c++) {
                acc[0][c] += xv0 * wv[c];
                acc[1][c] += xv1 * wv[c];
                acc[2][c] += xv2 * wv[c];
                acc[3][c] += xv3 * wv[c];
            }
        }
    }
    __syncthreads();
    // bias + relu -> back into xs
#pragma unroll
    for (int c = 0; c < 4; c++) {
        float b0 = bias[c0 + c];
        float b1 = bias[c0 + 128 + c];
#pragma unroll
        for (int r = 0; r < 4; r++) {
            xs[(r0 + r) * SH + c0 + c]       = fmaxf(acc[r][c]     + b0, 0.f);
            xs[(r0 + r) * SH + c0 + 128 + c] = fmaxf(acc[r][c + 4] + b1, 0.f);
        }
    }
    __syncthreads();
}

// ---------------------------------------------------------------------------
// Kernel 2: graph MLP. Grid (G/32, 2). Each CTA: 32 graphs x full 256 hidden
// for ONE branch b = blockIdx.y; writes outputs only where dataset_name==b.
// ---------------------------------------------------------------------------
__global__ void __launch_bounds__(256) graph_k(
    const int*   __restrict__ ds,
    const float* __restrict__ Wgs, const float* __restrict__ bgs,
    const float* __restrict__ Wgh, const float* __restrict__ bgh,
    float*       __restrict__ out)
{
    extern __shared__ float smem[];
    float* xs = smem;            // 32x256
    float* ws = smem + 32 * 256; // 16x256

    int g0  = blockIdx.x * 32;
    int b   = blockIdx.y;
    int tid = threadIdx.x;

    const float4* xsrc = (const float4*)(g_xg + (size_t)g0 * D);
    float4* xdst = (float4*)xs;
#pragma unroll
    for (int j = tid; j < 32 * D / 4; j += 256) xdst[j] = xsrc[j];
    // (first __syncthreads happens inside mlp1_core before first use)

    mlp1_core(xs, ws, Wgs + (size_t)b * D * SH, bgs + b * SH, tid);

    // layer 2: 32 graphs x 100 outputs, write only if ds matches branch
    const float* W2 = Wgh + (size_t)b * SH * (2 * HDG);
    for (int j = tid; j < 32 * 2 * HDG; j += 256) {
        int i = j / (2 * HDG);
        int h = j % (2 * HDG);
        int gg = g0 + i;
        if (ds[gg] != b) continue;
        float s = bgh[b * 2 * HDG + h];
#pragma unroll 8
        for (int k = 0; k < SH; k++) s += xs[i * SH + k] * W2[k * (2 * HDG) + h];
        if (h < HDG) out[OFF_GHEAD + gg * HDG + h] = s;
        else         out[OFF_GVAR  + gg * HDG + (h - HDG)] = s * s;
    }
}

// ---------------------------------------------------------------------------
// Kernel 3: node MLP (dominant). One CTA per graph -> branch uniform.
// Fused: x tile -> hidden(ReLU) in smem -> 256->6 layer-2 -> out.
// ---------------------------------------------------------------------------
__global__ void __launch_bounds__(256) node_k(
    const float* __restrict__ x,   const int*   __restrict__ ds,
    const float* __restrict__ Wn1, const float* __restrict__ bn1,
    const float* __restrict__ Wn2, const float* __restrict__ bn2,
    float*       __restrict__ out)
{
    extern __shared__ float smem[];
    float* xs = smem;            // 32x256
    float* ws = smem + 32 * 256; // 16x256

    int g   = blockIdx.x;
    int b   = ds[g];
    int tid = threadIdx.x;

    const float4* xsrc = (const float4*)(x + (size_t)g * NPG * D);
    float4* xdst = (float4*)xs;
#pragma unroll
    for (int j = tid; j < NPG * D / 4; j += 256) xdst[j] = xsrc[j];

    mlp1_core(xs, ws, Wn1 + (size_t)b * D * SH, bn1 + b * SH, tid);

    // layer 2: 32 nodes x 6 outputs (threads 0..191)
    if (tid < NPG * 2 * HDN) {
        int i = tid / (2 * HDN);
        int h = tid % (2 * HDN);
        const float* W2 = Wn2 + (size_t)b * SH * (2 * HDN);
        float s = bn2[b * 2 * HDN + h];
#pragma unroll 8
        for (int k = 0; k < SH; k++) s += xs[i * SH + k] * W2[k * (2 * HDN) + h];
        int node = g * NPG + i;
        if (h < HDN) out[OFF_NHEAD + node * HDN + h] = s;
        else         out[OFF_NVAR  + node * HDN + (h - HDN)] = s * s;
    }
}

// ---------------------------------------------------------------------------
extern "C" void kernel_launch(void* const* d_in, const int* in_sizes, int n_in,
                              void* d_out, int out_size)
{
    const float* x   = (const float*)d_in[0];
    const int*   ds  = (const int*)  d_in[1];
    // d_in[2] = batch: implied by structure (arange//32), not needed
    const float* Wgs = (const float*)d_in[3];
    const float* bgs = (const float*)d_in[4];
    const float* Wgh = (const float*)d_in[5];
    const float* bgh = (const float*)d_in[6];
    const float* Wn1 = (const float*)d_in[7];
    const float* bn1 = (const float*)d_in[8];
    const float* Wn2 = (const float*)d_in[9];
    const float* bn2 = (const float*)d_in[10];
    float* out = (float*)d_out;

    size_t smem = (32 * 256 + 16 * 256) * sizeof(float); // 48KB

    mean_k<<<G, 256>>>(x);
    graph_k<<<dim3(G / 32, 2), 256, smem>>>(ds, Wgs, bgs, Wgh, bgh, out);
    node_k<<<G, 256, smem>>>(x, ds, Wn1, bn1, Wn2, bn2, out);
}

// round 5
// speedup vs baseline: 1.7770x; 1.7770x over previous
#include <cuda_runtime.h>
#include <cuda_bf16.h>
#include <cstdint>

#define G    4096
#define NPG  32
#define NN   (G * NPG)
#define D    256
#define SH   256
#define HDG  50
#define HDN  3

#define OFF_GHEAD 0
#define OFF_NHEAD (G * HDG)
#define OFF_GVAR  (G * HDG + NN * HDN)
#define OFF_NVAR  (2 * G * HDG + NN * HDN)

#define NCTA   1056            // ceil-padded CTA count for node kernel
#define NSLOT  (NCTA * 4)      // 4224 schedule slots

__device__ float g_xg[G * D];
// W^T bf16 hi/lo, chunk-major: [branch][chunk(8)][split(2)][n(256)][k(32)]
__device__ unsigned short g_Wt[2][8][2][256][32];
__device__ int g_sched[NSLOT];
__device__ int g_cnt[2];

// ---------------- smem layout for node kernel (bytes) ----------------
#define KC    32
#define AP    40                      // padded K stride (halves)
#define SMA   0                       // A_s[2][128][40] bf16 = 20480
#define SMB   20480                   // B_s[2][256][40] bf16 = 40960
#define SMHS  0                       // hs[128][257] f32 = 131584 (aliases A/B)
#define SMW2  131584                  // W2s[256*6] f32 = 6144
#define SMBN  (131584 + 6144)         // bns[256]   f32 = 1024
#define SMTOT (131584 + 6144 + 1024)  // 138752

// ---------------- PTX helpers ----------------
__device__ __forceinline__ uint32_t smem_u32(const void* p) {
    uint32_t a;
    asm("{ .reg .u64 t; cvta.to.shared.u64 t, %1; cvt.u32.u64 %0, t; }" : "=r"(a) : "l"(p));
    return a;
}
__device__ __forceinline__ void ldsm4(uint32_t* r, uint32_t addr) {
    asm volatile("ldmatrix.sync.aligned.m8n8.x4.shared.b16 {%0,%1,%2,%3}, [%4];"
        : "=r"(r[0]), "=r"(r[1]), "=r"(r[2]), "=r"(r[3]) : "r"(addr));
}
__device__ __forceinline__ void ldsm2(uint32_t* r, uint32_t addr) {
    asm volatile("ldmatrix.sync.aligned.m8n8.x2.shared.b16 {%0,%1}, [%2];"
        : "=r"(r[0]), "=r"(r[1]) : "r"(addr));
}
__device__ __forceinline__ void mma_bf16(float* c, const uint32_t* a, const uint32_t* b) {
    asm volatile("mma.sync.aligned.m16n8k16.row.col.f32.bf16.bf16.f32 "
        "{%0,%1,%2,%3}, {%4,%5,%6,%7}, {%8,%9}, {%0,%1,%2,%3};"
        : "+f"(c[0]), "+f"(c[1]), "+f"(c[2]), "+f"(c[3])
        : "r"(a[0]), "r"(a[1]), "r"(a[2]), "r"(a[3]), "r"(b[0]), "r"(b[1]));
}
__device__ __forceinline__ uint32_t pack_bf16(float a, float b) {
    __nv_bfloat162 t = __floats2bfloat162_rn(a, b);
    return *(uint32_t*)&t;
}

// ---------------------------------------------------------------------------
// prep: split Wn1 into bf16 hi/lo W^T images, chunk-contiguous
// ---------------------------------------------------------------------------
__global__ void prep_k(const float* __restrict__ Wn1)
{
    int idx = blockIdx.x * blockDim.x + threadIdx.x;
    if (idx >= 2 * 256 * 256) return;
    int b = idx >> 16;
    int r = idx & 65535;
    int k = r >> 8;
    int n = r & 255;
    float v = Wn1[b * 65536 + k * 256 + n];
    __nv_bfloat16 h = __float2bfloat16(v);
    __nv_bfloat16 l = __float2bfloat16(v - __bfloat162float(h));
    int c = k >> 5, kk = k & 31;
    g_Wt[b][c][0][n][kk] = __bfloat16_as_ushort(h);
    g_Wt[b][c][1][n][kk] = __bfloat16_as_ushort(l);
}

// ---------------------------------------------------------------------------
// schedule: bucket graphs by branch (branch0 ascending, branch1 descending;
// >=128-slot gap of -1 in the middle guarantees no CTA mixes branches)
// ---------------------------------------------------------------------------
__global__ void sched_init_k()
{
    int i = blockIdx.x * blockDim.x + threadIdx.x;
    if (i < NSLOT) g_sched[i] = -1;
    if (i < 2) g_cnt[i] = 0;
}
__global__ void sched_fill_k(const int* __restrict__ ds)
{
    int g = blockIdx.x * blockDim.x + threadIdx.x;
    if (g >= G) return;
    if (ds[g] == 0) g_sched[atomicAdd(&g_cnt[0], 1)] = g;
    else            g_sched[NSLOT - 1 - atomicAdd(&g_cnt[1], 1)] = g;
}

// ---------------------------------------------------------------------------
// mean over 32 contiguous rows per graph
// ---------------------------------------------------------------------------
__global__ void mean_k(const float* __restrict__ x)
{
    int g = blockIdx.x;
    int d = threadIdx.x;
    const float* xp = x + (size_t)g * NPG * D + d;
    float s = 0.f;
#pragma unroll
    for (int i = 0; i < NPG; i++) s += xp[i * D];
    g_xg[g * D + d] = s * (1.0f / NPG);
}

// ---------------------------------------------------------------------------
// graph branch: SIMT fp32 (small fraction of total)
// ---------------------------------------------------------------------------
__device__ __forceinline__ void mlp1_core(
    float* __restrict__ xs, float* __restrict__ ws,
    const float* __restrict__ W, const float* __restrict__ bias, int tid)
{
    int r0 = (tid >> 5) * 4;
    int c0 = (tid & 31) * 4;
    float acc[4][8];
#pragma unroll
    for (int r = 0; r < 4; r++)
#pragma unroll
        for (int c = 0; c < 8; c++) acc[r][c] = 0.f;

    for (int kt = 0; kt < D; kt += 16) {
        __syncthreads();
        const float4* wsrc = (const float4*)(W + (size_t)kt * SH);
        float4* wdst = (float4*)ws;
#pragma unroll
        for (int j = tid; j < 16 * SH / 4; j += 256) wdst[j] = wsrc[j];
        __syncthreads();
#pragma unroll
        for (int dd = 0; dd < 16; dd++) {
            float xv0 = xs[(r0 + 0) * D + kt + dd];
            float xv1 = xs[(r0 + 1) * D + kt + dd];
            float xv2 = xs[(r0 + 2) * D + kt + dd];
            float xv3 = xs[(r0 + 3) * D + kt + dd];
            float4 wa = *(const float4*)&ws[dd * SH + c0];
            float4 wb = *(const float4*)&ws[dd * SH + c0 + 128];
            float wv[8] = {wa.x, wa.y, wa.z, wa.w, wb.x, wb.y, wb.z, wb.w};
#pragma unroll
            for (int c = 0; c < 8; c++) {
                acc[0][c] += xv0 * wv[c];
                acc[1][c] += xv1 * wv[c];
                acc[2][c] += xv2 * wv[c];
                acc[3][c] += xv3 * wv[c];
            }
        }
    }
    __syncthreads();
#pragma unroll
    for (int c = 0; c < 4; c++) {
        float b0 = bias[c0 + c];
        float b1 = bias[c0 + 128 + c];
#pragma unroll
        for (int r = 0; r < 4; r++) {
            xs[(r0 + r) * SH + c0 + c]       = fmaxf(acc[r][c]     + b0, 0.f);
            xs[(r0 + r) * SH + c0 + 128 + c] = fmaxf(acc[r][c + 4] + b1, 0.f);
        }
    }
    __syncthreads();
}

__global__ void __launch_bounds__(256) graph_k(
    const int* __restrict__ ds,
    const float* __restrict__ Wgs, const float* __restrict__ bgs,
    const float* __restrict__ Wgh, const float* __restrict__ bgh,
    float* __restrict__ out)
{
    extern __shared__ float smemf[];
    float* xs = smemf;
    float* ws = smemf + 32 * 256;

    int g0  = blockIdx.x * 32;
    int b   = blockIdx.y;
    int tid = threadIdx.x;

    const float4* xsrc = (const float4*)(g_xg + (size_t)g0 * D);
    float4* xdst = (float4*)xs;
#pragma unroll
    for (int j = tid; j < 32 * D / 4; j += 256) xdst[j] = xsrc[j];

    mlp1_core(xs, ws, Wgs + (size_t)b * D * SH, bgs + b * SH, tid);

    const float* W2 = Wgh + (size_t)b * SH * (2 * HDG);
    for (int j = tid; j < 32 * 2 * HDG; j += 256) {
        int i = j / (2 * HDG);
        int h = j % (2 * HDG);
        int gg = g0 + i;
        if (ds[gg] != b) continue;
        float s = bgh[b * 2 * HDG + h];
#pragma unroll 8
        for (int k = 0; k < SH; k++) s += xs[i * SH + k] * W2[k * (2 * HDG) + h];
        if (h < HDG) out[OFF_GHEAD + gg * HDG + h] = s;
        else         out[OFF_GVAR  + gg * HDG + (h - HDG)] = s * s;
    }
}

// ---------------------------------------------------------------------------
// node branch: bf16 mma.sync (HMMA), 3-term split, branch-sorted CTAs.
// CTA = 4 same-branch graphs = 128 nodes. 512 thr, warp grid 4(M)x4(N),
// warp tile 32x64. K chunked at 32, global->reg prefetch pipeline.
// ---------------------------------------------------------------------------
__global__ void __launch_bounds__(512, 1) node_mma_k(
    const float* __restrict__ x, const int* __restrict__ ds,
    const float* __restrict__ bn1, const float* __restrict__ Wn2,
    const float* __restrict__ bn2, float* __restrict__ out)
{
    extern __shared__ __align__(16) char smem[];
    uint32_t sbase = smem_u32(smem);
    int tid  = threadIdx.x;
    int lane = tid & 31;
    int wid  = tid >> 5;
    int mw   = wid >> 2;          // graph (M) warp index 0..3
    int nw   = wid & 3;           // N warp index 0..3

    int e[4];
#pragma unroll
    for (int r = 0; r < 4; r++) e[r] = g_sched[blockIdx.x * 4 + r];
    int b = -1;
#pragma unroll
    for (int r = 0; r < 4; r++) if (b < 0 && e[r] >= 0) b = ds[e[r]];
    if (b < 0) return;            // uniform: CTA fully in the -1 gap

    float* W2s = (float*)(smem + SMW2);
    float* bns = (float*)(smem + SMBN);
    for (int i = tid; i < 256 * 6; i += 512) W2s[i] = Wn2[b * 1536 + i];
    for (int i = tid; i < 256; i += 512)     bns[i] = bn1[b * 256 + i];

    float acc[2][8][4];
#pragma unroll
    for (int mt = 0; mt < 2; mt++)
#pragma unroll
        for (int nt = 0; nt < 8; nt++)
#pragma unroll
            for (int q = 0; q < 4; q++) acc[mt][nt][q] = 0.f;

    const float4* x4 = (const float4*)x;       // row stride 64 float4
    float4 av[2] = {make_float4(0, 0, 0, 0), make_float4(0, 0, 0, 0)};
    uint4  bv[4];

    // ---- prefetch chunk 0
    {
        const uint4* bp = (const uint4*)&g_Wt[b][0][0][0][0];
#pragma unroll
        for (int i = 0; i < 4; i++) bv[i] = bp[tid + 512 * i];
#pragma unroll
        for (int i = 0; i < 2; i++) {
            int idx = tid + 512 * i, row = idx >> 3, q = idx & 7;
            int g = e[row >> 5];
            if (g >= 0) av[i] = x4[(size_t)(g * 32 + (row & 31)) * 64 + q];
        }
    }

    for (int c = 0; c < 8; c++) {
        __syncthreads();          // previous chunk's ldmatrix done
        // store regs -> smem (A converted to bf16 hi/lo)
#pragma unroll
        for (int i = 0; i < 2; i++) {
            int idx = tid + 512 * i, row = idx >> 3, q = idx & 7;
            float4 v = av[i];
            float hx = __bfloat162float(__float2bfloat16(v.x));
            float hy = __bfloat162float(__float2bfloat16(v.y));
            float hz = __bfloat162float(__float2bfloat16(v.z));
            float hw = __bfloat162float(__float2bfloat16(v.w));
            uint2 hi = make_uint2(pack_bf16(v.x, v.y), pack_bf16(v.z, v.w));
            uint2 lo = make_uint2(pack_bf16(v.x - hx, v.y - hy),
                                  pack_bf16(v.z - hz, v.w - hw));
            *(uint2*)(smem + SMA + (row * AP + q * 4) * 2)           = hi;
            *(uint2*)(smem + SMA + ((128 + row) * AP + q * 4) * 2)   = lo;
        }
#pragma unroll
        for (int i = 0; i < 4; i++) {
            int idx = tid + 512 * i;
            int s = idx >> 10, rr = idx & 1023, n = rr >> 2, q = rr & 3;
            *(uint4*)(smem + SMB + ((s * 256 + n) * AP + q * 8) * 2) = bv[i];
        }
        __syncthreads();
        // prefetch next chunk
        if (c < 7) {
            const uint4* bp = (const uint4*)&g_Wt[b][c + 1][0][0][0];
#pragma unroll
            for (int i = 0; i < 4; i++) bv[i] = bp[tid + 512 * i];
#pragma unroll
            for (int i = 0; i < 2; i++) {
                int idx = tid + 512 * i, row = idx >> 3, q = idx & 7;
                int g = e[row >> 5];
                if (g >= 0) av[i] = x4[(size_t)(g * 32 + (row & 31)) * 64 + (c + 1) * 8 + q];
            }
        }
        // compute this chunk
#pragma unroll
        for (int ks = 0; ks < 2; ks++) {
            uint32_t Ah[2][4], Al[2][4];
#pragma unroll
            for (int mt = 0; mt < 2; mt++) {
                int arow = mw * 32 + mt * 16 + (lane & 15);
                int acol = ks * 16 + ((lane >> 4) << 3);
                ldsm4(Ah[mt], sbase + SMA + (uint32_t)((arow * AP + acol) * 2));
                ldsm4(Al[mt], sbase + SMA + (uint32_t)(((128 + arow) * AP + acol) * 2));
            }
#pragma unroll
            for (int nt = 0; nt < 8; nt++) {
                int brow = nw * 64 + nt * 8 + (lane & 7);
                int bcol = ks * 16 + (((lane >> 3) & 1) << 3);
                uint32_t Bh[2], Bl[2];
                ldsm2(Bh, sbase + SMB + (uint32_t)((brow * AP + bcol) * 2));
                ldsm2(Bl, sbase + SMB + (uint32_t)(((256 + brow) * AP + bcol) * 2));
#pragma unroll
                for (int mt = 0; mt < 2; mt++) {
                    mma_bf16(acc[mt][nt], Ah[mt], Bh);
                    mma_bf16(acc[mt][nt], Ah[mt], Bl);
                    mma_bf16(acc[mt][nt], Al[mt], Bh);
                }
            }
        }
    }

    __syncthreads();
    // bias + ReLU -> hs[128][257] (aliases A_s/B_s)
    float* hs = (float*)(smem + SMHS);
#pragma unroll
    for (int mt = 0; mt < 2; mt++)
#pragma unroll
        for (int nt = 0; nt < 8; nt++) {
            int row = mw * 32 + mt * 16 + (lane >> 2);
            int col = nw * 64 + nt * 8 + (lane & 3) * 2;
            const float* cc = acc[mt][nt];
            hs[row * 257 + col]           = fmaxf(cc[0] + bns[col],     0.f);
            hs[row * 257 + col + 1]       = fmaxf(cc[1] + bns[col + 1], 0.f);
            hs[(row + 8) * 257 + col]     = fmaxf(cc[2] + bns[col],     0.f);
            hs[(row + 8) * 257 + col + 1] = fmaxf(cc[3] + bns[col + 1], 0.f);
        }
    __syncthreads();

    if (tid < 128) {
        int g = e[tid >> 5];
        if (g >= 0) {
            float a0 = bn2[b * 6 + 0], a1 = bn2[b * 6 + 1], a2 = bn2[b * 6 + 2];
            float a3 = bn2[b * 6 + 3], a4 = bn2[b * 6 + 4], a5 = bn2[b * 6 + 5];
            const float* hrow = hs + tid * 257;
#pragma unroll 4
            for (int n = 0; n < 256; n++) {
                float hv = hrow[n];
                float2 w01 = *(const float2*)(W2s + n * 6);
                float2 w23 = *(const float2*)(W2s + n * 6 + 2);
                float2 w45 = *(const float2*)(W2s + n * 6 + 4);
                a0 += hv * w01.x; a1 += hv * w01.y; a2 += hv * w23.x;
                a3 += hv * w23.y; a4 += hv * w45.x; a5 += hv * w45.y;
            }
            int node = g * 32 + (tid & 31);
            out[OFF_NHEAD + node * 3 + 0] = a0;
            out[OFF_NHEAD + node * 3 + 1] = a1;
            out[OFF_NHEAD + node * 3 + 2] = a2;
            out[OFF_NVAR  + node * 3 + 0] = a3 * a3;
            out[OFF_NVAR  + node * 3 + 1] = a4 * a4;
            out[OFF_NVAR  + node * 3 + 2] = a5 * a5;
        }
    }
}

// ---------------------------------------------------------------------------
extern "C" void kernel_launch(void* const* d_in, const int* in_sizes, int n_in,
                              void* d_out, int out_size)
{
    const float* x   = (const float*)d_in[0];
    const int*   ds  = (const int*)  d_in[1];
    const float* Wgs = (const float*)d_in[3];
    const float* bgs = (const float*)d_in[4];
    const float* Wgh = (const float*)d_in[5];
    const float* bgh = (const float*)d_in[6];
    const float* Wn1 = (const float*)d_in[7];
    const float* bn1 = (const float*)d_in[8];
    const float* Wn2 = (const float*)d_in[9];
    const float* bn2 = (const float*)d_in[10];
    float* out = (float*)d_out;

    cudaFuncSetAttribute(node_mma_k, cudaFuncAttributeMaxDynamicSharedMemorySize, SMTOT);

    size_t smem_g = (32 * 256 + 16 * 256) * sizeof(float); // 48KB

    prep_k<<<512, 256>>>(Wn1);
    sched_init_k<<<17, 256>>>();
    sched_fill_k<<<16, 256>>>(ds);
    mean_k<<<G, 256>>>(x);
    graph_k<<<dim3(G / 32, 2), 256, smem_g>>>(ds, Wgs, bgs, Wgh, bgh, out);
    node_mma_k<<<NCTA, 512, SMTOT>>>(x, ds, bn1, Wn2, bn2, out);
}

// round 9
// speedup vs baseline: 2.0869x; 1.1744x over previous
#include <cuda_runtime.h>
#include <cuda_bf16.h>
#include <cstdint>

#define G    4096
#define NPG  32
#define NN   (G * NPG)
#define D    256
#define SH   256
#define HDG  50
#define HDN  3

#define OFF_GHEAD 0
#define OFF_NHEAD (G * HDG)
#define OFF_GVAR  (G * HDG + NN * HDN)
#define OFF_NVAR  (2 * G * HDG + NN * HDN)

#define NCTA   1056
#define NSLOT  (NCTA * 4)      // 4224; gap of 128 (-1) slots between branches

__device__ float g_xg[G * D];
// W^T bf16 hi/lo, chunk-major: [branch][chunk(8)][split(2)][n(256)][k(32)]
__device__ unsigned short g_Wt[2][8][2][256][32];
__device__ int g_sched[NSLOT];
__device__ int g_cnt[2];

// ---------------- node kernel smem layout (bytes) ----------------
#define SMA    0                      // A bufs: 2 x (256 rows x 80B) = 40960
#define SMB    40960                  // B bufs: 2 x (512 rows x 80B) = 81920
#define SMW2   122880                 // W2s[256*6] f32 = 6144
#define SMBN   129024                 // bns[256]  f32 = 1024
#define SMRED  130048                 // red[4][128][6] f32 = 12288
#define SMXP   142336                 // xg_part[8][4][256] f32 = 32768
#define SMGS   175104                 // gsm[4] int = 16
#define SMTOT  175136

// ---------------- PTX helpers ----------------
__device__ __forceinline__ uint32_t smem_u32(const void* p) {
    uint32_t a;
    asm("{ .reg .u64 t; cvta.to.shared.u64 t, %1; cvt.u32.u64 %0, t; }" : "=r"(a) : "l"(p));
    return a;
}
__device__ __forceinline__ void ldsm4(uint32_t* r, uint32_t addr) {
    asm volatile("ldmatrix.sync.aligned.m8n8.x4.shared.b16 {%0,%1,%2,%3}, [%4];"
        : "=r"(r[0]), "=r"(r[1]), "=r"(r[2]), "=r"(r[3]) : "r"(addr));
}
__device__ __forceinline__ void ldsm2(uint32_t* r, uint32_t addr) {
    asm volatile("ldmatrix.sync.aligned.m8n8.x2.shared.b16 {%0,%1}, [%2];"
        : "=r"(r[0]), "=r"(r[1]) : "r"(addr));
}
__device__ __forceinline__ void mma_bf16(float* c, const uint32_t* a, const uint32_t* b) {
    asm volatile("mma.sync.aligned.m16n8k16.row.col.f32.bf16.bf16.f32 "
        "{%0,%1,%2,%3}, {%4,%5,%6,%7}, {%8,%9}, {%0,%1,%2,%3};"
        : "+f"(c[0]), "+f"(c[1]), "+f"(c[2]), "+f"(c[3])
        : "r"(a[0]), "r"(a[1]), "r"(a[2]), "r"(a[3]), "r"(b[0]), "r"(b[1]));
}
__device__ __forceinline__ uint32_t pack_bf16(float a, float b) {
    __nv_bfloat162 t = __floats2bfloat162_rn(a, b);
    return *(uint32_t*)&t;
}
#define CP_ASYNC16(dst, src) \
    asm volatile("cp.async.cg.shared.global [%0], [%1], 16;" :: "r"(dst), "l"(src) : "memory")
#define CP_COMMIT()  asm volatile("cp.async.commit_group;" ::: "memory")
#define CP_WAIT0()   asm volatile("cp.async.wait_group 0;" ::: "memory")
#define CP_WAIT1()   asm volatile("cp.async.wait_group 1;" ::: "memory")

// ---------------------------------------------------------------------------
// prep: split Wn1 into bf16 hi/lo W^T images, chunk-contiguous
// ---------------------------------------------------------------------------
__global__ void prep_k(const float* __restrict__ Wn1)
{
    int idx = blockIdx.x * blockDim.x + threadIdx.x;
    if (idx >= 2 * 256 * 256) return;
    int b = idx >> 16;
    int r = idx & 65535;
    int k = r >> 8;
    int n = r & 255;
    float v = Wn1[b * 65536 + k * 256 + n];
    __nv_bfloat16 h = __float2bfloat16(v);
    __nv_bfloat16 l = __float2bfloat16(v - __bfloat162float(h));
    int c = k >> 5, kk = k & 31;
    g_Wt[b][c][0][n][kk] = __bfloat16_as_ushort(h);
    g_Wt[b][c][1][n][kk] = __bfloat16_as_ushort(l);
}

// ---------------------------------------------------------------------------
// schedule: bucket graphs by branch (branch0 ascending, branch1 descending)
// ---------------------------------------------------------------------------
__global__ void sched_init_k()
{
    int i = blockIdx.x * blockDim.x + threadIdx.x;
    if (i < NSLOT) g_sched[i] = -1;
    if (i < 2) g_cnt[i] = 0;
}
__global__ void sched_fill_k(const int* __restrict__ ds)
{
    int g = blockIdx.x * blockDim.x + threadIdx.x;
    if (g >= G) return;
    if (ds[g] == 0) g_sched[atomicAdd(&g_cnt[0], 1)] = g;
    else            g_sched[NSLOT - 1 - atomicAdd(&g_cnt[1], 1)] = g;
}

// ---------------------------------------------------------------------------
// node branch: bf16 HMMA, 3-term split, cp.async double-buffered B,
// fused per-graph mean (feeds graph_k), fused bias/ReLU/layer2 epilogue.
// CTA = 4 same-branch graphs = 128 nodes; 512 thr, warps 4(M) x 4(N).
// ---------------------------------------------------------------------------
__global__ void __launch_bounds__(512, 1) node_mma_k(
    const float* __restrict__ x, const int* __restrict__ ds,
    const float* __restrict__ bn1, const float* __restrict__ Wn2,
    const float* __restrict__ bn2, float* __restrict__ out)
{
    extern __shared__ __align__(16) char smem[];
    uint32_t sbase = smem_u32(smem);
    int tid  = threadIdx.x;
    int lane = tid & 31;
    int wid  = tid >> 5;
    int mw   = wid >> 2;
    int nw   = wid & 3;

    int* gsm = (int*)(smem + SMGS);
    if (tid < 4) gsm[tid] = g_sched[blockIdx.x * 4 + tid];
    __syncthreads();

    int b = -1, vmask = 0;
#pragma unroll
    for (int r = 0; r < 4; r++) {
        int g = gsm[r];
        if (g >= 0) { vmask |= 1 << r; if (b < 0) b = ds[g]; }
    }
    if (b < 0) return;

    float* W2s = (float*)(smem + SMW2);
    float* bns = (float*)(smem + SMBN);
    for (int i = tid; i < 256 * 6; i += 512) W2s[i] = Wn2[b * 1536 + i];
    if (tid < 256) bns[tid] = bn1[b * 256 + tid];

    float acc[2][8][4];
#pragma unroll
    for (int mt = 0; mt < 2; mt++)
#pragma unroll
        for (int nt = 0; nt < 8; nt++)
#pragma unroll
            for (int q = 0; q < 4; q++) acc[mt][nt][q] = 0.f;

    const float4* x4 = (const float4*)x;
    float4 av[2] = {make_float4(0,0,0,0), make_float4(0,0,0,0)};

    // ---- prologue: cp.async B chunk 0, LDG A chunk 0
    {
        const char* src = (const char*)&g_Wt[b][0][0][0][0];
#pragma unroll
        for (int i = 0; i < 4; i++) {
            int idx = tid + 512 * i;
            int s = idx >> 10, n = (idx >> 2) & 255, q = idx & 3;
            CP_ASYNC16(sbase + SMB + (uint32_t)((s * 256 + n) * 80 + q * 16),
                       src + idx * 16);
        }
        CP_COMMIT();
#pragma unroll
        for (int i = 0; i < 2; i++) {
            int idx = tid + 512 * i, row = idx >> 3, q = idx & 7;
            int g = gsm[row >> 5];
            if (g >= 0) av[i] = x4[(size_t)(g * 32 + (row & 31)) * 64 + q];
        }
    }

    for (int c = 0; c < 8; c++) {
        uint32_t abase = SMA + (uint32_t)(c & 1) * 20480;
        uint32_t bbase = SMB + (uint32_t)(c & 1) * 40960;
        // ---- convert + store A chunk c; accumulate mean partials
#pragma unroll
        for (int i = 0; i < 2; i++) {
            int idx = tid + 512 * i, row = idx >> 3, q = idx & 7;
            float4 v = av[i];
            float hx = __bfloat162float(__float2bfloat16(v.x));
            float hy = __bfloat162float(__float2bfloat16(v.y));
            float hz = __bfloat162float(__float2bfloat16(v.z));
            float hw = __bfloat162float(__float2bfloat16(v.w));
            uint2 hi = make_uint2(pack_bf16(v.x, v.y), pack_bf16(v.z, v.w));
            uint2 lo = make_uint2(pack_bf16(v.x - hx, v.y - hy),
                                  pack_bf16(v.z - hz, v.w - hw));
            *(uint2*)(smem + abase + (uint32_t)(row * 80 + q * 8))          = hi;
            *(uint2*)(smem + abase + (uint32_t)((128 + row) * 80 + q * 8))  = lo;
            // mean: reduce 4 consecutive rows (lanes ^8, ^16), store partial
            float vv[4] = {v.x, v.y, v.z, v.w};
#pragma unroll
            for (int t = 0; t < 4; t++) {
                float s = vv[t];
                s += __shfl_xor_sync(0xffffffffu, s, 8);
                s += __shfl_xor_sync(0xffffffffu, s, 16);
                if ((lane & 24) == 0) {
                    int gl = row >> 5;
                    if ((vmask >> gl) & 1) {
                        int p = (row >> 2) & 7;
                        ((float*)(smem + SMXP))[(p * 4 + gl) * 256 + c * 32 + q * 4 + t] = s;
                    }
                }
            }
        }
        // ---- prefetch chunk c+1
        if (c < 7) {
            const char* src = (const char*)&g_Wt[b][c + 1][0][0][0];
            uint32_t nb = SMB + (uint32_t)((c + 1) & 1) * 40960;
#pragma unroll
            for (int i = 0; i < 4; i++) {
                int idx = tid + 512 * i;
                int s = idx >> 10, n = (idx >> 2) & 255, q = idx & 3;
                CP_ASYNC16(sbase + nb + (uint32_t)((s * 256 + n) * 80 + q * 16),
                           src + idx * 16);
            }
            CP_COMMIT();
#pragma unroll
            for (int i = 0; i < 2; i++) {
                int idx = tid + 512 * i, row = idx >> 3, q = idx & 7;
                int g = gsm[row >> 5];
                if (g >= 0) av[i] = x4[(size_t)(g * 32 + (row & 31)) * 64 + (c + 1) * 8 + q];
            }
            CP_WAIT1();
        } else {
            CP_WAIT0();
        }
        __syncthreads();
        // ---- compute chunk c
#pragma unroll
        for (int ks = 0; ks < 2; ks++) {
            uint32_t Ah[2][4], Al[2][4];
#pragma unroll
            for (int mt = 0; mt < 2; mt++) {
                int arow = mw * 32 + mt * 16 + (lane & 15);
                int acol = ks * 16 + ((lane >> 4) << 3);
                ldsm4(Ah[mt], sbase + abase + (uint32_t)(arow * 80 + acol * 2));
                ldsm4(Al[mt], sbase + abase + (uint32_t)((128 + arow) * 80 + acol * 2));
            }
#pragma unroll
            for (int nt = 0; nt < 8; nt++) {
                int brow = nw * 64 + nt * 8 + (lane & 7);
                int bcol = ks * 16 + (((lane >> 3) & 1) << 3);
                uint32_t Bh[2], Bl[2];
                ldsm2(Bh, sbase + bbase + (uint32_t)(brow * 80 + bcol * 2));
                ldsm2(Bl, sbase + bbase + (uint32_t)((256 + brow) * 80 + bcol * 2));
#pragma unroll
                for (int mt = 0; mt < 2; mt++) {
                    mma_bf16(acc[mt][nt], Ah[mt], Bh);
                    mma_bf16(acc[mt][nt], Ah[mt], Bl);
                    mma_bf16(acc[mt][nt], Al[mt], Bh);
                }
            }
        }
        if (c < 7) __syncthreads();   // protect next chunk's buffer writes
    }

    // ---- epilogue: bias+ReLU on fragments, partial layer2, reduce
    float pt[4][6];
#pragma unroll
    for (int r = 0; r < 4; r++)
#pragma unroll
        for (int j = 0; j < 6; j++) pt[r][j] = 0.f;

#pragma unroll
    for (int mt = 0; mt < 2; mt++)
#pragma unroll
        for (int nt = 0; nt < 8; nt++) {
            int col = nw * 64 + nt * 8 + (lane & 3) * 2;
            float h00 = fmaxf(acc[mt][nt][0] + bns[col],     0.f);
            float h01 = fmaxf(acc[mt][nt][1] + bns[col + 1], 0.f);
            float h10 = fmaxf(acc[mt][nt][2] + bns[col],     0.f);
            float h11 = fmaxf(acc[mt][nt][3] + bns[col + 1], 0.f);
#pragma unroll
            for (int j = 0; j < 6; j++) {
                float w0 = W2s[col * 6 + j], w1 = W2s[(col + 1) * 6 + j];
                pt[mt * 2][j]     += h00 * w0 + h01 * w1;
                pt[mt * 2 + 1][j] += h10 * w0 + h11 * w1;
            }
        }

    float* red = (float*)(smem + SMRED);
#pragma unroll
    for (int r = 0; r < 4; r++)
#pragma unroll
        for (int j = 0; j < 6; j++) {
            float s = pt[r][j];
            s += __shfl_xor_sync(0xffffffffu, s, 1);
            s += __shfl_xor_sync(0xffffffffu, s, 2);
            if ((lane & 3) == 0) {
                int row = mw * 32 + (r >> 1) * 16 + (lane >> 2) + (r & 1) * 8;
                red[(nw * 128 + row) * 6 + j] = s;
            }
        }
    __syncthreads();

    if (tid < 128) {
        int g = gsm[tid >> 5];
        if (g >= 0) {
            float o[6];
#pragma unroll
            for (int j = 0; j < 6; j++)
                o[j] = bn2[b * 6 + j] + red[tid * 6 + j] + red[(128 + tid) * 6 + j]
                     + red[(256 + tid) * 6 + j] + red[(384 + tid) * 6 + j];
            int node = g * 32 + (tid & 31);
            out[OFF_NHEAD + node * 3 + 0] = o[0];
            out[OFF_NHEAD + node * 3 + 1] = o[1];
            out[OFF_NHEAD + node * 3 + 2] = o[2];
            out[OFF_NVAR  + node * 3 + 0] = o[3] * o[3];
            out[OFF_NVAR  + node * 3 + 1] = o[4] * o[4];
            out[OFF_NVAR  + node * 3 + 2] = o[5] * o[5];
        }
    }

    // ---- write per-graph means (deterministic tree over 8 partials)
    const float* xp = (const float*)(smem + SMXP);
#pragma unroll
    for (int t = tid; t < 1024; t += 512) {
        int gl = t >> 8, d = t & 255;
        int g = gsm[gl];
        if (g >= 0) {
            float s = 0.f;
#pragma unroll
            for (int p = 0; p < 8; p++) s += xp[(p * 4 + gl) * 256 + d];
            g_xg[g * 256 + d] = s * (1.0f / NPG);
        }
    }
}

// ---------------------------------------------------------------------------
// graph branch: SIMT fp32, branch-sorted (132 CTAs x 32 graphs, one branch).
// W tile = 8 rows -> dynamic smem 40KB; total with static gidx stays well
// under the 48KB no-opt-in limit (static+dynamic is what the launch checks).
// ---------------------------------------------------------------------------
__global__ void __launch_bounds__(256) graph_k(
    const int* __restrict__ ds,
    const float* __restrict__ Wgs, const float* __restrict__ bgs,
    const float* __restrict__ Wgh, const float* __restrict__ bgh,
    float* __restrict__ out)
{
    extern __shared__ float smemf[];
    __shared__ int gidx[32];
    float* xs = smemf;                 // 32x256 = 32KB
    float* ws = smemf + 32 * 256;      // 8x256  = 8KB

    int tid = threadIdx.x;
    if (tid < 32) gidx[tid] = g_sched[blockIdx.x * 32 + tid];
    __syncthreads();

    int b = -1;
    for (int r = 0; r < 32; r++) {
        int g = gidx[r];
        if (g >= 0) { b = ds[g]; break; }
    }
    if (b < 0) return;

    // gather xg rows
    for (int j = tid; j < 32 * 64; j += 256) {
        int row = j >> 6, q = j & 63;
        int g = gidx[row];
        if (g >= 0) ((float4*)xs)[j] = ((const float4*)g_xg)[g * 64 + q];
    }

    {
        const float* W = Wgs + (size_t)b * D * SH;
        const float* bias = bgs + b * SH;
        int r0 = (tid >> 5) * 4;
        int c0 = (tid & 31) * 4;
        float acc[4][8];
#pragma unroll
        for (int r = 0; r < 4; r++)
#pragma unroll
            for (int c = 0; c < 8; c++) acc[r][c] = 0.f;

        for (int kt = 0; kt < D; kt += 8) {
            __syncthreads();
            const float4* wsrc = (const float4*)(W + (size_t)kt * SH);
            float4* wdst = (float4*)ws;
#pragma unroll
            for (int j = tid; j < 8 * SH / 4; j += 256) wdst[j] = wsrc[j];
            __syncthreads();
#pragma unroll
            for (int dd = 0; dd < 8; dd++) {
                float xv0 = xs[(r0 + 0) * D + kt + dd];
                float xv1 = xs[(r0 + 1) * D + kt + dd];
                float xv2 = xs[(r0 + 2) * D + kt + dd];
                float xv3 = xs[(r0 + 3) * D + kt + dd];
                float4 wa = *(const float4*)&ws[dd * SH + c0];
                float4 wb = *(const float4*)&ws[dd * SH + c0 + 128];
                float wv[8] = {wa.x, wa.y, wa.z, wa.w, wb.x, wb.y, wb.z, wb.w};
#pragma unroll
                for (int c = 0; c < 8; c++) {
                    acc[0][c] += xv0 * wv[c];
                    acc[1][c] += xv1 * wv[c];
                    acc[2][c] += xv2 * wv[c];
                    acc[3][c] += xv3 * wv[c];
                }
            }
        }
        __syncthreads();
#pragma unroll
        for (int c = 0; c < 4; c++) {
            float b0 = bias[c0 + c];
            float b1 = bias[c0 + 128 + c];
#pragma unroll
            for (int r = 0; r < 4; r++) {
                xs[(r0 + r) * SH + c0 + c]       = fmaxf(acc[r][c]     + b0, 0.f);
                xs[(r0 + r) * SH + c0 + 128 + c] = fmaxf(acc[r][c + 4] + b1, 0.f);
            }
        }
        __syncthreads();
    }

    const float* W2 = Wgh + (size_t)b * SH * (2 * HDG);
    for (int j = tid; j < 32 * 2 * HDG; j += 256) {
        int i = j / (2 * HDG);
        int h = j % (2 * HDG);
        int g = gidx[i];
        if (g < 0) continue;
        float s = bgh[b * 2 * HDG + h];
#pragma unroll 8
        for (int k = 0; k < SH; k++) s += xs[i * SH + k] * W2[k * (2 * HDG) + h];
        if (h < HDG) out[OFF_GHEAD + g * HDG + h] = s;
        else         out[OFF_GVAR  + g * HDG + (h - HDG)] = s * s;
    }
}

// ---------------------------------------------------------------------------
extern "C" void kernel_launch(void* const* d_in, const int* in_sizes, int n_in,
                              void* d_out, int out_size)
{
    const float* x   = (const float*)d_in[0];
    const int*   ds  = (const int*)  d_in[1];
    const float* Wgs = (const float*)d_in[3];
    const float* bgs = (const float*)d_in[4];
    const float* Wgh = (const float*)d_in[5];
    const float* bgh = (const float*)d_in[6];
    const float* Wn1 = (const float*)d_in[7];
    const float* bn1 = (const float*)d_in[8];
    const float* Wn2 = (const float*)d_in[9];
    const float* bn2 = (const float*)d_in[10];
    float* out = (float*)d_out;

    cudaFuncSetAttribute(node_mma_k, cudaFuncAttributeMaxDynamicSharedMemorySize, SMTOT);

    size_t smem_g = (32 * 256 + 8 * 256) * sizeof(float);   // 40KB dynamic

    prep_k<<<512, 256>>>(Wn1);
    sched_init_k<<<17, 256>>>();
    sched_fill_k<<<16, 256>>>(ds);
    node_mma_k<<<NCTA, 512, SMTOT>>>(x, ds, bn1, Wn2, bn2, out);
    graph_k<<<NSLOT / 32, 256, smem_g>>>(ds, Wgs, bgs, Wgh, bgh, out);
}